// round 13
// baseline (speedup 1.0000x reference)
#include <cuda_runtime.h>

#define NN_ 100000
#define NE_ 1600000
#define INF_ 128
#define HC_ 64
#define OC_ 32

// ---------------- scratch (static device globals; no allocation) ----------------
__device__ __align__(16) float  g_xl1[NN_ * HC_];   // x @ W1     (25.6 MB)
__device__ __align__(16) float  g_h1 [NN_ * HC_];   // relu(gat1) (25.6 MB)
__device__ __align__(16) float  g_xl2[NN_ * OC_];   // h @ W2     (12.8 MB)
__device__ float  g_as1[NN_ * 2];                   // layer1 per-node scores
__device__ float  g_ad1[NN_ * 2];
__device__ float  g_as2[NN_];
__device__ float  g_ad2[NN_];
__device__ int    g_deg[NN_];
__device__ int    g_ptr[NN_];
__device__ int    g_cur[NN_];
__device__ int    g_total;
__device__ __align__(16) float4 g_erec[NE_];        // {src, ex0, ex1, -} (25.6 MB)

__device__ __forceinline__ float lrelu(float x) { return x > 0.f ? x : 0.2f * x; }

typedef unsigned long long ull;
__device__ __forceinline__ ull pk2(float x, float y) {
    ull r; asm("mov.b64 %0,{%1,%2};" : "=l"(r) : "f"(x), "f"(y)); return r;
}
__device__ __forceinline__ void up2(ull v, float& x, float& y) {
    asm("mov.b64 {%0,%1},%2;" : "=f"(x), "=f"(y) : "l"(v));
}
// packed fp32x2 FMA (FFMA2): d.lo=fma(a.lo,b.lo,c.lo), d.hi likewise
__device__ __forceinline__ ull f2fma(ull a, ull b, ull c) {
    ull d; asm("fma.rn.f32x2 %0,%1,%2,%3;" : "=l"(d) : "l"(a), "l"(b), "l"(c)); return d;
}

// ---------------- capture-fork resources (created once, at load time) --------
// Streams/events are host-side driver objects (no tracked device memory);
// created before the harness's first mem checkpoint. Never destroyed.
static cudaStream_t g_s2;
static cudaEvent_t  g_evA, g_evB;
static int          g_streams_ok = 0;
namespace {
struct _StreamInit {
    _StreamInit() {
        if (cudaStreamCreateWithFlags(&g_s2, cudaStreamNonBlocking) == cudaSuccess &&
            cudaEventCreateWithFlags(&g_evA, cudaEventDisableTiming) == cudaSuccess &&
            cudaEventCreateWithFlags(&g_evB, cudaEventDisableTiming) == cudaSuccess)
            g_streams_ok = 1;
    }
};
_StreamInit _stream_init;
}

// ---------------- CSR build (no global scans; bins in arbitrary order) -------
__global__ void prep_kernel() {
    int i = blockIdx.x * blockDim.x + threadIdx.x;
    if (i < NN_) g_deg[i] = 0;
    if (i == 0) g_total = 0;
}
__global__ void hist_kernel(const int* __restrict__ dst) {
    int i = blockIdx.x * blockDim.x + threadIdx.x;
    if (i < NE_) atomicAdd(&g_deg[dst[i]], 1);
}
// Hierarchical bin offsets: block-local smem scan + ONE atomic per block.
__global__ void ptr_kernel() {
    __shared__ int sdeg[256];
    __shared__ int sbase;
    int t = threadIdx.x;
    int i = blockIdx.x * 256 + t;
    int d = (i < NN_) ? g_deg[i] : 0;
    sdeg[t] = d;
    __syncthreads();
    for (int off = 1; off < 256; off <<= 1) {   // Hillis-Steele inclusive scan
        int u = (t >= off) ? sdeg[t - off] : 0;
        __syncthreads();
        sdeg[t] += u;
        __syncthreads();
    }
    if (t == 255) sbase = atomicAdd(&g_total, sdeg[255]);
    __syncthreads();
    if (i < NN_) {
        int p = sbase + sdeg[t] - d;            // exclusive prefix + block base
        g_ptr[i] = p;
        g_cur[i] = p;                           // scatter cursor starts at bin base
    }
}
// scatter edges into bins; one packed 16B record per edge (1 L2 sector)
__global__ void scatter_kernel(const int* __restrict__ src,
                               const int* __restrict__ dst) {
    int i = blockIdx.x * blockDim.x + threadIdx.x;
    if (i >= NE_) return;
    int s = src[i], d = dst[i];
    int p = atomicAdd(&g_cur[d], 1);
    if (p < 0 || p >= NE_) return;               // defensive: never corrupt memory
    float e0 = g_as1[s * 2 + 0] + g_ad1[d * 2 + 0];
    float e1 = g_as1[s * 2 + 1] + g_ad1[d * 2 + 1];
    g_erec[p] = make_float4(__int_as_float(s),
                            __expf(lrelu(e0)), __expf(lrelu(e1)), 0.f);
}

// ---------------- GEMM1 + scores1 fused (FFMA2, 8x8, reg prefetch) ----------
#define XP_ 260
__global__ void __launch_bounds__(256, 2)
gemm1_kernel(const float* __restrict__ x, const float* __restrict__ W1,
             const float* __restrict__ as, const float* __restrict__ ad) {
    __shared__ float ws[INF_ * HC_];   // 32 KB, [k][c]
    __shared__ float xs[8 * XP_];      // 8.3 KB, [k_local][row(padded)]
    __shared__ float sa[HC_], sd[HC_];
    int t = threadIdx.x;
    int tx = t & 7, ty = t >> 3;
    int row0 = blockIdx.x * 256;

    if (t < HC_) { sa[t] = as[t]; sd[t] = ad[t]; }
    for (int i = t; i < INF_ * HC_ / 4; i += 256)
        ((float4*)ws)[i] = ((const float4*)W1)[i];

    int r0 = t >> 1,          q0 = t & 1;
    int r1 = (t + 256) >> 1,  q1 = (t + 256) & 1;
    int gr0 = row0 + r0, gr1 = row0 + r1;
    const float4 z4 = make_float4(0.f, 0.f, 0.f, 0.f);

    float4 pre0 = (gr0 < NN_) ? ((const float4*)x)[gr0 * 32 + q0] : z4;
    float4 pre1 = (gr1 < NN_) ? ((const float4*)x)[gr1 * 32 + q1] : z4;

    ull acc[4][8];                     // [row-pair][col]
#pragma unroll
    for (int a = 0; a < 4; a++)
#pragma unroll
        for (int b = 0; b < 8; b++) acc[a][b] = 0ull;

    for (int c = 0; c < 16; c++) {     // 16 chunks of 8 k
        __syncthreads();
        xs[(4 * q0 + 0) * XP_ + r0] = pre0.x;
        xs[(4 * q0 + 1) * XP_ + r0] = pre0.y;
        xs[(4 * q0 + 2) * XP_ + r0] = pre0.z;
        xs[(4 * q0 + 3) * XP_ + r0] = pre0.w;
        xs[(4 * q1 + 0) * XP_ + r1] = pre1.x;
        xs[(4 * q1 + 1) * XP_ + r1] = pre1.y;
        xs[(4 * q1 + 2) * XP_ + r1] = pre1.z;
        xs[(4 * q1 + 3) * XP_ + r1] = pre1.w;
        __syncthreads();
        if (c < 15) {
            pre0 = (gr0 < NN_) ? ((const float4*)x)[gr0 * 32 + (c + 1) * 2 + q0] : z4;
            pre1 = (gr1 < NN_) ? ((const float4*)x)[gr1 * 32 + (c + 1) * 2 + q1] : z4;
        }
#pragma unroll
        for (int k = 0; k < 8; k++) {
            const ull* ap = (const ull*)&xs[k * XP_ + ty * 8];
            ull a0 = ap[0], a1 = ap[1], a2 = ap[2], a3 = ap[3];
            const float* wr = &ws[(c * 8 + k) * HC_ + tx * 8];
            float4 b0 = *(const float4*)&wr[0];
            float4 b1 = *(const float4*)&wr[4];
            ull p0 = pk2(b0.x, b0.x), p1 = pk2(b0.y, b0.y);
            ull p2 = pk2(b0.z, b0.z), p3 = pk2(b0.w, b0.w);
            ull p4 = pk2(b1.x, b1.x), p5 = pk2(b1.y, b1.y);
            ull p6 = pk2(b1.z, b1.z), p7 = pk2(b1.w, b1.w);
            ull av[4] = {a0, a1, a2, a3};
#pragma unroll
            for (int p = 0; p < 4; p++) {
                ull a = av[p];
                acc[p][0] = f2fma(a, p0, acc[p][0]);
                acc[p][1] = f2fma(a, p1, acc[p][1]);
                acc[p][2] = f2fma(a, p2, acc[p][2]);
                acc[p][3] = f2fma(a, p3, acc[p][3]);
                acc[p][4] = f2fma(a, p4, acc[p][4]);
                acc[p][5] = f2fma(a, p5, acc[p][5]);
                acc[p][6] = f2fma(a, p6, acc[p][6]);
                acc[p][7] = f2fma(a, p7, acc[p][7]);
            }
        }
    }
#pragma unroll
    for (int p = 0; p < 4; p++) {
        float lo[8], hi[8];
#pragma unroll
        for (int cc = 0; cc < 8; cc++) up2(acc[p][cc], lo[cc], hi[cc]);
#pragma unroll
        for (int half = 0; half < 2; half++) {
            const float* v = half ? hi : lo;
            int n = row0 + ty * 8 + 2 * p + half;
            float pas = 0.f, pad = 0.f;
#pragma unroll
            for (int cc = 0; cc < 8; cc++) {
                pas = fmaf(v[cc], sa[tx * 8 + cc], pas);
                pad = fmaf(v[cc], sd[tx * 8 + cc], pad);
            }
            pas += __shfl_xor_sync(0xffffffffu, pas, 1);
            pas += __shfl_xor_sync(0xffffffffu, pas, 2);
            pad += __shfl_xor_sync(0xffffffffu, pad, 1);
            pad += __shfl_xor_sync(0xffffffffu, pad, 2);
            if (n < NN_) {
                *(float4*)&g_xl1[n * HC_ + tx * 8] =
                    make_float4(v[0], v[1], v[2], v[3]);
                *(float4*)&g_xl1[n * HC_ + tx * 8 + 4] =
                    make_float4(v[4], v[5], v[6], v[7]);
                if (tx == 0 || tx == 4) {
                    int h = tx >> 2;
                    g_as1[n * 2 + h] = pas;
                    g_ad1[n * 2 + h] = pad;
                }
            }
        }
    }
}

// ---------------- GEMM2 + scores2 fused (FFMA2, 8x8, BM=512) ----------------
#define XP2_ 516
__global__ void __launch_bounds__(256, 2)
gemm2_kernel(const float* __restrict__ W2,
             const float* __restrict__ as, const float* __restrict__ ad) {
    __shared__ float ws[HC_ * OC_];    //  8 KB, [k][c]
    __shared__ float xs[8 * XP2_];     // 16.5 KB, [k_local][row(padded)]
    __shared__ float sa[OC_], sd[OC_];
    int t = threadIdx.x;
    int tx = t & 3, ty = t >> 2;
    int row0 = blockIdx.x * 512;

    if (t < OC_) { sa[t] = as[t]; sd[t] = ad[t]; }
    for (int i = t; i < HC_ * OC_ / 4; i += 256)
        ((float4*)ws)[i] = ((const float4*)W2)[i];

    int rr[4], qq[4], gg[4];
#pragma unroll
    for (int rep = 0; rep < 4; rep++) {
        int idx = t + rep * 256;
        rr[rep] = idx >> 1; qq[rep] = idx & 1; gg[rep] = row0 + rr[rep];
    }
    const float4 z4 = make_float4(0.f, 0.f, 0.f, 0.f);
    float4 pre[4];
#pragma unroll
    for (int rep = 0; rep < 4; rep++)
        pre[rep] = (gg[rep] < NN_) ? ((const float4*)g_h1)[gg[rep] * 16 + qq[rep]] : z4;

    ull acc[4][8];
#pragma unroll
    for (int a = 0; a < 4; a++)
#pragma unroll
        for (int b = 0; b < 8; b++) acc[a][b] = 0ull;

    for (int c = 0; c < 8; c++) {      // 8 chunks of 8 k
        __syncthreads();
#pragma unroll
        for (int rep = 0; rep < 4; rep++) {
            int r = rr[rep], q = qq[rep];
            xs[(4 * q + 0) * XP2_ + r] = pre[rep].x;
            xs[(4 * q + 1) * XP2_ + r] = pre[rep].y;
            xs[(4 * q + 2) * XP2_ + r] = pre[rep].z;
            xs[(4 * q + 3) * XP2_ + r] = pre[rep].w;
        }
        __syncthreads();
        if (c < 7) {
#pragma unroll
            for (int rep = 0; rep < 4; rep++)
                pre[rep] = (gg[rep] < NN_)
                    ? ((const float4*)g_h1)[gg[rep] * 16 + (c + 1) * 2 + qq[rep]] : z4;
        }
#pragma unroll
        for (int k = 0; k < 8; k++) {
            const ull* ap = (const ull*)&xs[k * XP2_ + ty * 8];
            ull a0 = ap[0], a1 = ap[1], a2 = ap[2], a3 = ap[3];
            const float* wr = &ws[(c * 8 + k) * OC_ + tx * 8];
            float4 b0 = *(const float4*)&wr[0];
            float4 b1 = *(const float4*)&wr[4];
            ull p0 = pk2(b0.x, b0.x), p1 = pk2(b0.y, b0.y);
            ull p2 = pk2(b0.z, b0.z), p3 = pk2(b0.w, b0.w);
            ull p4 = pk2(b1.x, b1.x), p5 = pk2(b1.y, b1.y);
            ull p6 = pk2(b1.z, b1.z), p7 = pk2(b1.w, b1.w);
            ull av[4] = {a0, a1, a2, a3};
#pragma unroll
            for (int p = 0; p < 4; p++) {
                ull a = av[p];
                acc[p][0] = f2fma(a, p0, acc[p][0]);
                acc[p][1] = f2fma(a, p1, acc[p][1]);
                acc[p][2] = f2fma(a, p2, acc[p][2]);
                acc[p][3] = f2fma(a, p3, acc[p][3]);
                acc[p][4] = f2fma(a, p4, acc[p][4]);
                acc[p][5] = f2fma(a, p5, acc[p][5]);
                acc[p][6] = f2fma(a, p6, acc[p][6]);
                acc[p][7] = f2fma(a, p7, acc[p][7]);
            }
        }
    }
#pragma unroll
    for (int p = 0; p < 4; p++) {
        float lo[8], hi[8];
#pragma unroll
        for (int cc = 0; cc < 8; cc++) up2(acc[p][cc], lo[cc], hi[cc]);
#pragma unroll
        for (int half = 0; half < 2; half++) {
            const float* v = half ? hi : lo;
            int n = row0 + ty * 8 + 2 * p + half;
            float pas = 0.f, pad = 0.f;
#pragma unroll
            for (int cc = 0; cc < 8; cc++) {
                pas = fmaf(v[cc], sa[tx * 8 + cc], pas);
                pad = fmaf(v[cc], sd[tx * 8 + cc], pad);
            }
            pas += __shfl_xor_sync(0xffffffffu, pas, 1);
            pas += __shfl_xor_sync(0xffffffffu, pas, 2);
            pad += __shfl_xor_sync(0xffffffffu, pad, 1);
            pad += __shfl_xor_sync(0xffffffffu, pad, 2);
            if (n < NN_) {
                *(float4*)&g_xl2[n * OC_ + tx * 8] =
                    make_float4(v[0], v[1], v[2], v[3]);
                *(float4*)&g_xl2[n * OC_ + tx * 8 + 4] =
                    make_float4(v[4], v[5], v[6], v[7]);
                if (tx == 0) { g_as2[n] = pas; g_ad2[n] = pad; }
            }
        }
    }
}

// ---------------- layer-1 aggregation (warp per dst, smem-staged batches) ----
__global__ void __launch_bounds__(256, 4)
agg1_kernel(const float* __restrict__ b1) {
    __shared__ float4 stg[8][32];
    int g = blockIdx.x * blockDim.x + threadIdx.x;
    int n = g >> 5, lane = g & 31, wid = (threadIdx.x >> 5);
    if (n >= NN_) return;
    float ex0 = __expf(lrelu(g_as1[n * 2 + 0] + g_ad1[n * 2 + 0]));  // self loop
    float ex1 = __expf(lrelu(g_as1[n * 2 + 1] + g_ad1[n * 2 + 1]));
    float den0 = ex0, den1 = ex1;
    const float2* xl = (const float2*)g_xl1;
    float2 v = xl[n * 32 + lane];
    bool h0 = lane < 16;
    float exm = h0 ? ex0 : ex1;
    float ax = exm * v.x, ay = exm * v.y;
    int st = g_ptr[n], de = g_deg[n];
    for (int base = 0; base < de; base += 32) {
        int m = min(32, de - base);
        if (lane < m) stg[wid][lane] = g_erec[st + base + lane];
        __syncwarp();
#pragma unroll 4
        for (int j = 0; j < m; j++) {
            float4 r = stg[wid][j];              // LDS broadcast
            int s = __float_as_int(r.x);
            den0 += r.y; den1 += r.z;
            float2 w = xl[s * 32 + lane];        // 256B row gather
            float fm = h0 ? r.y : r.z;
            ax = fmaf(fm, w.x, ax);
            ay = fmaf(fm, w.y, ay);
        }
        __syncwarp();
    }
    float den = h0 ? den0 : den1;
    float inv = 1.f / (den + 1e-16f);
    float bx = b1[lane * 2], by = b1[lane * 2 + 1];
    float2 o;
    o.x = fmaxf(fmaf(ax, inv, bx), 0.f);   // bias + ReLU fused
    o.y = fmaxf(fmaf(ay, inv, by), 0.f);
    ((float2*)g_h1)[n * 32 + lane] = o;
}

// ---------------- layer-2 aggregation (exp fused, smem-staged) --------------
__global__ void __launch_bounds__(256, 4)
agg2_kernel(const float* __restrict__ b2, float* __restrict__ out) {
    __shared__ float2 stg[8][32];
    int g = blockIdx.x * blockDim.x + threadIdx.x;
    int n = g >> 5, lane = g & 31, wid = (threadIdx.x >> 5);
    if (n >= NN_) return;
    float ad2n = g_ad2[n];
    float ex = __expf(lrelu(g_as2[n] + ad2n));   // self loop
    float den = ex;
    float acc = ex * g_xl2[n * OC_ + lane];
    int st = g_ptr[n], de = g_deg[n];
    for (int base = 0; base < de; base += 32) {
        int m = min(32, de - base);
        if (lane < m) {
            float4 r = g_erec[st + base + lane];
            int s = __float_as_int(r.x);
            float e = __expf(lrelu(g_as2[s] + ad2n));
            stg[wid][lane] = make_float2(r.x, e);
        }
        __syncwarp();
#pragma unroll 4
        for (int j = 0; j < m; j++) {
            float2 r = stg[wid][j];              // LDS broadcast
            int s = __float_as_int(r.x);
            den += r.y;
            acc = fmaf(r.y, g_xl2[s * OC_ + lane], acc);   // 128B row gather
        }
        __syncwarp();
    }
    out[n * OC_ + lane] = acc / (den + 1e-16f) + b2[lane];
}

// ---------------- launch ----------------
extern "C" void kernel_launch(void* const* d_in, const int* in_sizes, int n_in,
                              void* d_out, int out_size) {
    // size-keyed input remap with positional fallback
    const float* x = 0; const int* ei = 0;
    const float* W1 = 0; const float* W2 = 0;
    const float* a64[3] = {0, 0, 0}; int n64 = 0;
    const float* a32[3] = {0, 0, 0}; int n32 = 0;
    for (int i = 0; i < n_in; i++) {
        int sz = in_sizes[i];
        if      (sz == NN_ * INF_) x  = (const float*)d_in[i];
        else if (sz == 2 * NE_)    ei = (const int*)  d_in[i];
        else if (sz == INF_ * HC_) W1 = (const float*)d_in[i];
        else if (sz == HC_ * OC_)  W2 = (const float*)d_in[i];
        else if (sz == HC_) { if (n64 < 3) a64[n64++] = (const float*)d_in[i]; }
        else if (sz == OC_) { if (n32 < 3) a32[n32++] = (const float*)d_in[i]; }
    }
    if (!x)  x  = (const float*)d_in[0];
    if (!ei) ei = (const int*)  d_in[1];
    if (!W1) W1 = (const float*)d_in[2];
    if (!W2) W2 = (const float*)d_in[6];
    const float* as1 = a64[0] ? a64[0] : (const float*)d_in[3];
    const float* ad1 = a64[1] ? a64[1] : (const float*)d_in[4];
    const float* b1  = a64[2] ? a64[2] : (const float*)d_in[5];
    const float* as2 = a32[0] ? a32[0] : (const float*)d_in[7];
    const float* ad2 = a32[1] ? a32[1] : (const float*)d_in[8];
    const float* b2  = a32[2] ? a32[2] : (const float*)d_in[9];
    float* out = (float*)d_out;

    const int* srcp = ei;
    const int* dstp = ei + NE_;

    const int NB  = (NN_ + 255) / 256;         // node blocks
    const int EB  = (NE_ + 255) / 256;         // edge blocks
    const int G1  = (NN_ + 255) / 256;         // 391 gemm1 blocks (256 rows)
    const int G2  = (NN_ + 511) / 512;         // 196 gemm2 blocks (512 rows)
    const int WB  = (NN_ * 32 + 255) / 256;    // 12500 warp-per-node blocks

    if (g_streams_ok) {
        // fork: CSR build {prep->hist->ptr} runs concurrently with gemm1;
        // both join before scatter (the only consumer of both).
        cudaEventRecord(g_evA, 0);
        cudaStreamWaitEvent(g_s2, g_evA, 0);
        prep_kernel<<<NB, 256, 0, g_s2>>>();
        hist_kernel<<<EB, 256, 0, g_s2>>>(dstp);
        ptr_kernel<<<NB, 256, 0, g_s2>>>();
        cudaEventRecord(g_evB, g_s2);
        gemm1_kernel<<<G1, 256>>>(x, W1, as1, ad1);
        cudaStreamWaitEvent(0, g_evB, 0);
    } else {
        prep_kernel<<<NB, 256>>>();
        hist_kernel<<<EB, 256>>>(dstp);
        ptr_kernel<<<NB, 256>>>();
        gemm1_kernel<<<G1, 256>>>(x, W1, as1, ad1);
    }

    scatter_kernel<<<EB, 256>>>(srcp, dstp);
    agg1_kernel<<<WB, 256>>>(b1);

    gemm2_kernel<<<G2, 256>>>(W2, as2, ad2);
    agg2_kernel<<<WB, 256>>>(b2, out);

    (void)n_in; (void)out_size;
}

// round 15
// speedup vs baseline: 1.4409x; 1.4409x over previous
#include <cuda_runtime.h>

#define NN_ 100000
#define NE_ 1600000
#define INF_ 128
#define HC_ 64
#define OC_ 32

// ---------------- scratch (static device globals; no allocation) ----------------
__device__ __align__(16) float  g_xl1[NN_ * HC_];   // x @ W1     (25.6 MB)
__device__ __align__(16) float  g_h1 [NN_ * HC_];   // relu(gat1) (25.6 MB)
__device__ __align__(16) float  g_xl2[NN_ * OC_];   // h @ W2     (12.8 MB)
__device__ float  g_as1[NN_ * 2];                   // layer1 per-node scores
__device__ float  g_ad1[NN_ * 2];
__device__ float  g_as2[NN_];
__device__ float  g_ad2[NN_];
__device__ int    g_deg[NN_];
__device__ int    g_ptr[NN_];
__device__ int    g_cur[NN_];
__device__ int    g_total;
__device__ __align__(16) float4 g_erec[NE_];        // {src, ex0, ex1, -} (25.6 MB)

__device__ __forceinline__ float lrelu(float x) { return x > 0.f ? x : 0.2f * x; }

typedef unsigned long long ull;
__device__ __forceinline__ ull pk2(float x, float y) {
    ull r; asm("mov.b64 %0,{%1,%2};" : "=l"(r) : "f"(x), "f"(y)); return r;
}
__device__ __forceinline__ void up2(ull v, float& x, float& y) {
    asm("mov.b64 {%0,%1},%2;" : "=f"(x), "=f"(y) : "l"(v));
}
// packed fp32x2 FMA (FFMA2): d.lo=fma(a.lo,b.lo,c.lo), d.hi likewise
__device__ __forceinline__ ull f2fma(ull a, ull b, ull c) {
    ull d; asm("fma.rn.f32x2 %0,%1,%2,%3;" : "=l"(d) : "l"(a), "l"(b), "l"(c)); return d;
}

// ---------------- CSR build (no global scans; bins in arbitrary order) -------
__global__ void prep_kernel() {
    int i = blockIdx.x * blockDim.x + threadIdx.x;
    if (i < NN_) g_deg[i] = 0;
    if (i == 0) g_total = 0;
}
__global__ void hist_kernel(const int* __restrict__ dst) {
    int i = blockIdx.x * blockDim.x + threadIdx.x;
    if (i < NE_) atomicAdd(&g_deg[dst[i]], 1);
}
// Hierarchical bin offsets: block-local smem scan + ONE atomic per block.
__global__ void ptr_kernel() {
    __shared__ int sdeg[256];
    __shared__ int sbase;
    int t = threadIdx.x;
    int i = blockIdx.x * 256 + t;
    int d = (i < NN_) ? g_deg[i] : 0;
    sdeg[t] = d;
    __syncthreads();
    for (int off = 1; off < 256; off <<= 1) {   // Hillis-Steele inclusive scan
        int u = (t >= off) ? sdeg[t - off] : 0;
        __syncthreads();
        sdeg[t] += u;
        __syncthreads();
    }
    if (t == 255) sbase = atomicAdd(&g_total, sdeg[255]);
    __syncthreads();
    if (i < NN_) {
        int p = sbase + sdeg[t] - d;            // exclusive prefix + block base
        g_ptr[i] = p;
        g_cur[i] = p;                           // scatter cursor starts at bin base
    }
}
// scatter edges into bins; one packed 16B record per edge (1 L2 sector)
__global__ void scatter_kernel(const int* __restrict__ src,
                               const int* __restrict__ dst) {
    int i = blockIdx.x * blockDim.x + threadIdx.x;
    if (i >= NE_) return;
    int s = src[i], d = dst[i];
    int p = atomicAdd(&g_cur[d], 1);
    if (p < 0 || p >= NE_) return;               // defensive: never corrupt memory
    float e0 = g_as1[s * 2 + 0] + g_ad1[d * 2 + 0];
    float e1 = g_as1[s * 2 + 1] + g_ad1[d * 2 + 1];
    g_erec[p] = make_float4(__int_as_float(s),
                            __expf(lrelu(e0)), __expf(lrelu(e1)), 0.f);
}

// ---------------- GEMM1 + scores1 fused (FFMA2, 8x4 tile, 3 CTAs/SM) --------
// xl1[N][64] = x[N][128] @ W1[128][64]; scores fused in epilogue.
// 256 threads: tx=t&15 owns 4 cols, ty=t>>4 owns 8 rows (128-row tile).
// 8x4 tile (16 ull acc) frees ~32 regs vs 8x8 -> 3 CTAs/SM (6 warps/SMSP)
// for latency hiding; prior evidence: occ 21.5%, issue 32% = stall-bound.
#define XP_ 132
__global__ void __launch_bounds__(256, 3)
gemm1_kernel(const float* __restrict__ x, const float* __restrict__ W1,
             const float* __restrict__ as, const float* __restrict__ ad) {
    __shared__ float ws[INF_ * HC_];   // 32 KB, [k][c]
    __shared__ float xs[8 * XP_];      // 4.2 KB, [k_local][row(padded)]
    __shared__ float sa[HC_], sd[HC_];
    int t = threadIdx.x;
    int tx = t & 15, ty = t >> 4;
    int row0 = blockIdx.x * 128;

    if (t < HC_) { sa[t] = as[t]; sd[t] = ad[t]; }
    for (int i = t; i < INF_ * HC_ / 4; i += 256)
        ((float4*)ws)[i] = ((const float4*)W1)[i];

    // per-thread A-load coordinates (1 float4 per chunk: 128 rows x 2 f4)
    int r0 = t >> 1, q0 = t & 1;
    int gr0 = row0 + r0;
    const float4 z4 = make_float4(0.f, 0.f, 0.f, 0.f);
    float4 pre0 = (gr0 < NN_) ? ((const float4*)x)[gr0 * 32 + q0] : z4;

    ull acc[4][4];                     // [row-pair][col]
#pragma unroll
    for (int a = 0; a < 4; a++)
#pragma unroll
        for (int b = 0; b < 4; b++) acc[a][b] = 0ull;

    for (int c = 0; c < 16; c++) {     // 16 chunks of 8 k
        __syncthreads();
        xs[(4 * q0 + 0) * XP_ + r0] = pre0.x;   // transpose into [k][row]
        xs[(4 * q0 + 1) * XP_ + r0] = pre0.y;
        xs[(4 * q0 + 2) * XP_ + r0] = pre0.z;
        xs[(4 * q0 + 3) * XP_ + r0] = pre0.w;
        __syncthreads();
        if (c < 15)
            pre0 = (gr0 < NN_) ? ((const float4*)x)[gr0 * 32 + (c + 1) * 2 + q0] : z4;
#pragma unroll
        for (int k = 0; k < 8; k++) {
            const ull* ap = (const ull*)&xs[k * XP_ + ty * 8];   // 4 row-pairs
            ull a0 = ap[0], a1 = ap[1], a2 = ap[2], a3 = ap[3];
            float4 b = *(const float4*)&ws[(c * 8 + k) * HC_ + tx * 4];
            ull p0 = pk2(b.x, b.x), p1 = pk2(b.y, b.y);
            ull p2 = pk2(b.z, b.z), p3 = pk2(b.w, b.w);
            ull av[4] = {a0, a1, a2, a3};
#pragma unroll
            for (int p = 0; p < 4; p++) {
                ull a = av[p];
                acc[p][0] = f2fma(a, p0, acc[p][0]);
                acc[p][1] = f2fma(a, p1, acc[p][1]);
                acc[p][2] = f2fma(a, p2, acc[p][2]);
                acc[p][3] = f2fma(a, p3, acc[p][3]);
            }
        }
    }
    // epilogue: unpack row-pairs, store + fused scores.
    // Lanes 0-15 share rows (ty even base), as do 16-31; head0 = tx 0-7
    // (cols 0-31), head1 = tx 8-15. shfl offsets 1,2,4 stay in-group.
#pragma unroll
    for (int p = 0; p < 4; p++) {
        float lo[4], hi[4];
#pragma unroll
        for (int cc = 0; cc < 4; cc++) up2(acc[p][cc], lo[cc], hi[cc]);
#pragma unroll
        for (int half = 0; half < 2; half++) {
            const float* v = half ? hi : lo;
            int n = row0 + ty * 8 + 2 * p + half;
            float pas = 0.f, pad = 0.f;
#pragma unroll
            for (int cc = 0; cc < 4; cc++) {
                pas = fmaf(v[cc], sa[tx * 4 + cc], pas);
                pad = fmaf(v[cc], sd[tx * 4 + cc], pad);
            }
            pas += __shfl_xor_sync(0xffffffffu, pas, 1);
            pas += __shfl_xor_sync(0xffffffffu, pas, 2);
            pas += __shfl_xor_sync(0xffffffffu, pas, 4);
            pad += __shfl_xor_sync(0xffffffffu, pad, 1);
            pad += __shfl_xor_sync(0xffffffffu, pad, 2);
            pad += __shfl_xor_sync(0xffffffffu, pad, 4);
            if (n < NN_) {
                *(float4*)&g_xl1[n * HC_ + tx * 4] =
                    make_float4(v[0], v[1], v[2], v[3]);
                if (tx == 0 || tx == 8) {        // tx<8: head0, tx>=8: head1
                    int h = tx >> 3;
                    g_as1[n * 2 + h] = pas;
                    g_ad1[n * 2 + h] = pad;
                }
            }
        }
    }
}

// ---------------- GEMM2 + scores2 fused (FFMA2, 8x8, BM=512) ----------------
#define XP2_ 516
__global__ void __launch_bounds__(256, 2)
gemm2_kernel(const float* __restrict__ W2,
             const float* __restrict__ as, const float* __restrict__ ad) {
    __shared__ float ws[HC_ * OC_];    //  8 KB, [k][c]
    __shared__ float xs[8 * XP2_];     // 16.5 KB, [k_local][row(padded)]
    __shared__ float sa[OC_], sd[OC_];
    int t = threadIdx.x;
    int tx = t & 3, ty = t >> 2;
    int row0 = blockIdx.x * 512;

    if (t < OC_) { sa[t] = as[t]; sd[t] = ad[t]; }
    for (int i = t; i < HC_ * OC_ / 4; i += 256)
        ((float4*)ws)[i] = ((const float4*)W2)[i];

    int rr[4], qq[4], gg[4];
#pragma unroll
    for (int rep = 0; rep < 4; rep++) {
        int idx = t + rep * 256;
        rr[rep] = idx >> 1; qq[rep] = idx & 1; gg[rep] = row0 + rr[rep];
    }
    const float4 z4 = make_float4(0.f, 0.f, 0.f, 0.f);
    float4 pre[4];
#pragma unroll
    for (int rep = 0; rep < 4; rep++)
        pre[rep] = (gg[rep] < NN_) ? ((const float4*)g_h1)[gg[rep] * 16 + qq[rep]] : z4;

    ull acc[4][8];
#pragma unroll
    for (int a = 0; a < 4; a++)
#pragma unroll
        for (int b = 0; b < 8; b++) acc[a][b] = 0ull;

    for (int c = 0; c < 8; c++) {      // 8 chunks of 8 k
        __syncthreads();
#pragma unroll
        for (int rep = 0; rep < 4; rep++) {
            int r = rr[rep], q = qq[rep];
            xs[(4 * q + 0) * XP2_ + r] = pre[rep].x;
            xs[(4 * q + 1) * XP2_ + r] = pre[rep].y;
            xs[(4 * q + 2) * XP2_ + r] = pre[rep].z;
            xs[(4 * q + 3) * XP2_ + r] = pre[rep].w;
        }
        __syncthreads();
        if (c < 7) {
#pragma unroll
            for (int rep = 0; rep < 4; rep++)
                pre[rep] = (gg[rep] < NN_)
                    ? ((const float4*)g_h1)[gg[rep] * 16 + (c + 1) * 2 + qq[rep]] : z4;
        }
#pragma unroll
        for (int k = 0; k < 8; k++) {
            const ull* ap = (const ull*)&xs[k * XP2_ + ty * 8];
            ull a0 = ap[0], a1 = ap[1], a2 = ap[2], a3 = ap[3];
            const float* wr = &ws[(c * 8 + k) * OC_ + tx * 8];
            float4 b0 = *(const float4*)&wr[0];
            float4 b1 = *(const float4*)&wr[4];
            ull p0 = pk2(b0.x, b0.x), p1 = pk2(b0.y, b0.y);
            ull p2 = pk2(b0.z, b0.z), p3 = pk2(b0.w, b0.w);
            ull p4 = pk2(b1.x, b1.x), p5 = pk2(b1.y, b1.y);
            ull p6 = pk2(b1.z, b1.z), p7 = pk2(b1.w, b1.w);
            ull av[4] = {a0, a1, a2, a3};
#pragma unroll
            for (int p = 0; p < 4; p++) {
                ull a = av[p];
                acc[p][0] = f2fma(a, p0, acc[p][0]);
                acc[p][1] = f2fma(a, p1, acc[p][1]);
                acc[p][2] = f2fma(a, p2, acc[p][2]);
                acc[p][3] = f2fma(a, p3, acc[p][3]);
                acc[p][4] = f2fma(a, p4, acc[p][4]);
                acc[p][5] = f2fma(a, p5, acc[p][5]);
                acc[p][6] = f2fma(a, p6, acc[p][6]);
                acc[p][7] = f2fma(a, p7, acc[p][7]);
            }
        }
    }
#pragma unroll
    for (int p = 0; p < 4; p++) {
        float lo[8], hi[8];
#pragma unroll
        for (int cc = 0; cc < 8; cc++) up2(acc[p][cc], lo[cc], hi[cc]);
#pragma unroll
        for (int half = 0; half < 2; half++) {
            const float* v = half ? hi : lo;
            int n = row0 + ty * 8 + 2 * p + half;
            float pas = 0.f, pad = 0.f;
#pragma unroll
            for (int cc = 0; cc < 8; cc++) {
                pas = fmaf(v[cc], sa[tx * 8 + cc], pas);
                pad = fmaf(v[cc], sd[tx * 8 + cc], pad);
            }
            pas += __shfl_xor_sync(0xffffffffu, pas, 1);
            pas += __shfl_xor_sync(0xffffffffu, pas, 2);
            pad += __shfl_xor_sync(0xffffffffu, pad, 1);
            pad += __shfl_xor_sync(0xffffffffu, pad, 2);
            if (n < NN_) {
                *(float4*)&g_xl2[n * OC_ + tx * 8] =
                    make_float4(v[0], v[1], v[2], v[3]);
                *(float4*)&g_xl2[n * OC_ + tx * 8 + 4] =
                    make_float4(v[4], v[5], v[6], v[7]);
                if (tx == 0) { g_as2[n] = pas; g_ad2[n] = pad; }
            }
        }
    }
}

// ---------------- layer-1 aggregation (warp per dst, smem-staged batches) ----
__global__ void __launch_bounds__(256, 4)
agg1_kernel(const float* __restrict__ b1) {
    __shared__ float4 stg[8][32];
    int g = blockIdx.x * blockDim.x + threadIdx.x;
    int n = g >> 5, lane = g & 31, wid = (threadIdx.x >> 5);
    if (n >= NN_) return;
    float ex0 = __expf(lrelu(g_as1[n * 2 + 0] + g_ad1[n * 2 + 0]));  // self loop
    float ex1 = __expf(lrelu(g_as1[n * 2 + 1] + g_ad1[n * 2 + 1]));
    float den0 = ex0, den1 = ex1;
    const float2* xl = (const float2*)g_xl1;
    float2 v = xl[n * 32 + lane];
    bool h0 = lane < 16;
    float exm = h0 ? ex0 : ex1;
    float ax = exm * v.x, ay = exm * v.y;
    int st = g_ptr[n], de = g_deg[n];
    for (int base = 0; base < de; base += 32) {
        int m = min(32, de - base);
        if (lane < m) stg[wid][lane] = g_erec[st + base + lane];
        __syncwarp();
#pragma unroll 4
        for (int j = 0; j < m; j++) {
            float4 r = stg[wid][j];              // LDS broadcast
            int s = __float_as_int(r.x);
            den0 += r.y; den1 += r.z;
            float2 w = xl[s * 32 + lane];        // 256B row gather
            float fm = h0 ? r.y : r.z;
            ax = fmaf(fm, w.x, ax);
            ay = fmaf(fm, w.y, ay);
        }
        __syncwarp();
    }
    float den = h0 ? den0 : den1;
    float inv = 1.f / (den + 1e-16f);
    float bx = b1[lane * 2], by = b1[lane * 2 + 1];
    float2 o;
    o.x = fmaxf(fmaf(ax, inv, bx), 0.f);   // bias + ReLU fused
    o.y = fmaxf(fmaf(ay, inv, by), 0.f);
    ((float2*)g_h1)[n * 32 + lane] = o;
}

// ---------------- layer-2 aggregation (exp fused, smem-staged) --------------
__global__ void __launch_bounds__(256, 4)
agg2_kernel(const float* __restrict__ b2, float* __restrict__ out) {
    __shared__ float2 stg[8][32];
    int g = blockIdx.x * blockDim.x + threadIdx.x;
    int n = g >> 5, lane = g & 31, wid = (threadIdx.x >> 5);
    if (n >= NN_) return;
    float ad2n = g_ad2[n];
    float ex = __expf(lrelu(g_as2[n] + ad2n));   // self loop
    float den = ex;
    float acc = ex * g_xl2[n * OC_ + lane];
    int st = g_ptr[n], de = g_deg[n];
    for (int base = 0; base < de; base += 32) {
        int m = min(32, de - base);
        if (lane < m) {
            float4 r = g_erec[st + base + lane];
            int s = __float_as_int(r.x);
            float e = __expf(lrelu(g_as2[s] + ad2n));
            stg[wid][lane] = make_float2(r.x, e);
        }
        __syncwarp();
#pragma unroll 4
        for (int j = 0; j < m; j++) {
            float2 r = stg[wid][j];              // LDS broadcast
            int s = __float_as_int(r.x);
            den += r.y;
            acc = fmaf(r.y, g_xl2[s * OC_ + lane], acc);   // 128B row gather
        }
        __syncwarp();
    }
    out[n * OC_ + lane] = acc / (den + 1e-16f) + b2[lane];
}

// ---------------- launch ----------------
extern "C" void kernel_launch(void* const* d_in, const int* in_sizes, int n_in,
                              void* d_out, int out_size) {
    // size-keyed input remap with positional fallback
    const float* x = 0; const int* ei = 0;
    const float* W1 = 0; const float* W2 = 0;
    const float* a64[3] = {0, 0, 0}; int n64 = 0;
    const float* a32[3] = {0, 0, 0}; int n32 = 0;
    for (int i = 0; i < n_in; i++) {
        int sz = in_sizes[i];
        if      (sz == NN_ * INF_) x  = (const float*)d_in[i];
        else if (sz == 2 * NE_)    ei = (const int*)  d_in[i];
        else if (sz == INF_ * HC_) W1 = (const float*)d_in[i];
        else if (sz == HC_ * OC_)  W2 = (const float*)d_in[i];
        else if (sz == HC_) { if (n64 < 3) a64[n64++] = (const float*)d_in[i]; }
        else if (sz == OC_) { if (n32 < 3) a32[n32++] = (const float*)d_in[i]; }
    }
    if (!x)  x  = (const float*)d_in[0];
    if (!ei) ei = (const int*)  d_in[1];
    if (!W1) W1 = (const float*)d_in[2];
    if (!W2) W2 = (const float*)d_in[6];
    const float* as1 = a64[0] ? a64[0] : (const float*)d_in[3];
    const float* ad1 = a64[1] ? a64[1] : (const float*)d_in[4];
    const float* b1  = a64[2] ? a64[2] : (const float*)d_in[5];
    const float* as2 = a32[0] ? a32[0] : (const float*)d_in[7];
    const float* ad2 = a32[1] ? a32[1] : (const float*)d_in[8];
    const float* b2  = a32[2] ? a32[2] : (const float*)d_in[9];
    float* out = (float*)d_out;

    const int* srcp = ei;
    const int* dstp = ei + NE_;

    const int NB  = (NN_ + 255) / 256;         // node blocks
    const int EB  = (NE_ + 255) / 256;         // edge blocks
    const int G1  = (NN_ + 127) / 128;         // 782 gemm1 blocks (128 rows)
    const int G2  = (NN_ + 511) / 512;         // 196 gemm2 blocks (512 rows)
    const int WB  = (NN_ * 32 + 255) / 256;    // 12500 warp-per-node blocks

    // sequential pipeline (R13 fork experiment regressed: hist || gemm1
    // contend for L2; reverted)
    prep_kernel<<<NB, 256>>>();
    hist_kernel<<<EB, 256>>>(dstp);
    ptr_kernel<<<NB, 256>>>();

    gemm1_kernel<<<G1, 256>>>(x, W1, as1, ad1);
    scatter_kernel<<<EB, 256>>>(srcp, dstp);
    agg1_kernel<<<WB, 256>>>(b1);

    gemm2_kernel<<<G2, 256>>>(W2, as2, ad2);
    agg2_kernel<<<WB, 256>>>(b2, out);

    (void)n_in; (void)out_size;
}

// round 16
// speedup vs baseline: 1.5276x; 1.0601x over previous
#include <cuda_runtime.h>

#define NN_ 100000
#define NE_ 1600000
#define INF_ 128
#define HC_ 64
#define OC_ 32

// ---------------- scratch (static device globals; no allocation) ----------------
__device__ __align__(16) float  g_xl1[NN_ * HC_];   // x @ W1     (25.6 MB)
__device__ __align__(16) float  g_h1 [NN_ * HC_];   // relu(gat1) (25.6 MB)
__device__ __align__(16) float  g_xl2[NN_ * OC_];   // h @ W2     (12.8 MB)
__device__ __align__(8) float  g_as1[NN_ * 2];      // layer1 per-node scores
__device__ __align__(8) float  g_ad1[NN_ * 2];
__device__ float  g_as2[NN_];
__device__ float  g_ad2[NN_];
__device__ int    g_deg[NN_];
__device__ int    g_ptr[NN_];
__device__ int    g_cur[NN_];
__device__ int    g_total;
__device__ int    g_esrc[NE_];                      // 4B/edge record (src only)

__device__ __forceinline__ float lrelu(float x) { return x > 0.f ? x : 0.2f * x; }

typedef unsigned long long ull;
__device__ __forceinline__ ull pk2(float x, float y) {
    ull r; asm("mov.b64 %0,{%1,%2};" : "=l"(r) : "f"(x), "f"(y)); return r;
}
__device__ __forceinline__ void up2(ull v, float& x, float& y) {
    asm("mov.b64 {%0,%1},%2;" : "=f"(x), "=f"(y) : "l"(v));
}
// packed fp32x2 FMA (FFMA2): d.lo=fma(a.lo,b.lo,c.lo), d.hi likewise
__device__ __forceinline__ ull f2fma(ull a, ull b, ull c) {
    ull d; asm("fma.rn.f32x2 %0,%1,%2,%3;" : "=l"(d) : "l"(a), "l"(b), "l"(c)); return d;
}

// ---------------- CSR build (no global scans; bins in arbitrary order) -------
__global__ void prep_kernel() {
    int i = blockIdx.x * blockDim.x + threadIdx.x;
    if (i < NN_) g_deg[i] = 0;
    if (i == 0) g_total = 0;
}
__global__ void hist_kernel(const int* __restrict__ dst) {
    int i = blockIdx.x * blockDim.x + threadIdx.x;
    if (i < NE_) atomicAdd(&g_deg[dst[i]], 1);
}
// Hierarchical bin offsets: block-local smem scan + ONE atomic per block.
__global__ void ptr_kernel() {
    __shared__ int sdeg[256];
    __shared__ int sbase;
    int t = threadIdx.x;
    int i = blockIdx.x * 256 + t;
    int d = (i < NN_) ? g_deg[i] : 0;
    sdeg[t] = d;
    __syncthreads();
    for (int off = 1; off < 256; off <<= 1) {   // Hillis-Steele inclusive scan
        int u = (t >= off) ? sdeg[t - off] : 0;
        __syncthreads();
        sdeg[t] += u;
        __syncthreads();
    }
    if (t == 255) sbase = atomicAdd(&g_total, sdeg[255]);
    __syncthreads();
    if (i < NN_) {
        int p = sbase + sdeg[t] - d;            // exclusive prefix + block base
        g_ptr[i] = p;
        g_cur[i] = p;                           // scatter cursor starts at bin base
    }
}
// scatter edges into bins: 4B record (src only) — exp is computed at agg time
// by the staging lane (dst == bin owner there), so scatter reads no scores.
__global__ void scatter_kernel(const int* __restrict__ src,
                               const int* __restrict__ dst) {
    int i = blockIdx.x * blockDim.x + threadIdx.x;
    if (i >= NE_) return;
    int s = src[i], d = dst[i];
    int p = atomicAdd(&g_cur[d], 1);
    if (p < 0 || p >= NE_) return;               // defensive: never corrupt memory
    g_esrc[p] = s;
}

// ---------------- GEMM1 + scores1 fused (FFMA2, 8x4 tile, 4 CTAs/SM) --------
// xl1[N][64] = x[N][128] @ W1[128][64]; scores fused in epilogue.
// occupancy lever confirmed (2->3 CTAs: 59.7->53.1us); try 4 CTAs (<=64 regs).
#define XP_ 132
__global__ void __launch_bounds__(256, 4)
gemm1_kernel(const float* __restrict__ x, const float* __restrict__ W1,
             const float* __restrict__ as, const float* __restrict__ ad) {
    __shared__ float ws[INF_ * HC_];   // 32 KB, [k][c]
    __shared__ float xs[8 * XP_];      // 4.2 KB, [k_local][row(padded)]
    __shared__ float sa[HC_], sd[HC_];
    int t = threadIdx.x;
    int tx = t & 15, ty = t >> 4;
    int row0 = blockIdx.x * 128;

    if (t < HC_) { sa[t] = as[t]; sd[t] = ad[t]; }
    for (int i = t; i < INF_ * HC_ / 4; i += 256)
        ((float4*)ws)[i] = ((const float4*)W1)[i];

    // per-thread A-load coordinates (1 float4 per chunk: 128 rows x 2 f4)
    int r0 = t >> 1, q0 = t & 1;
    int gr0 = row0 + r0;
    const float4 z4 = make_float4(0.f, 0.f, 0.f, 0.f);
    float4 pre0 = (gr0 < NN_) ? ((const float4*)x)[gr0 * 32 + q0] : z4;

    ull acc[4][4];                     // [row-pair][col]
#pragma unroll
    for (int a = 0; a < 4; a++)
#pragma unroll
        for (int b = 0; b < 4; b++) acc[a][b] = 0ull;

    for (int c = 0; c < 16; c++) {     // 16 chunks of 8 k
        __syncthreads();
        xs[(4 * q0 + 0) * XP_ + r0] = pre0.x;   // transpose into [k][row]
        xs[(4 * q0 + 1) * XP_ + r0] = pre0.y;
        xs[(4 * q0 + 2) * XP_ + r0] = pre0.z;
        xs[(4 * q0 + 3) * XP_ + r0] = pre0.w;
        __syncthreads();
        if (c < 15)
            pre0 = (gr0 < NN_) ? ((const float4*)x)[gr0 * 32 + (c + 1) * 2 + q0] : z4;
#pragma unroll
        for (int k = 0; k < 8; k++) {
            const ull* ap = (const ull*)&xs[k * XP_ + ty * 8];   // 4 row-pairs
            ull a0 = ap[0], a1 = ap[1], a2 = ap[2], a3 = ap[3];
            float4 b = *(const float4*)&ws[(c * 8 + k) * HC_ + tx * 4];
            ull p0 = pk2(b.x, b.x), p1 = pk2(b.y, b.y);
            ull p2 = pk2(b.z, b.z), p3 = pk2(b.w, b.w);
            ull av[4] = {a0, a1, a2, a3};
#pragma unroll
            for (int p = 0; p < 4; p++) {
                ull a = av[p];
                acc[p][0] = f2fma(a, p0, acc[p][0]);
                acc[p][1] = f2fma(a, p1, acc[p][1]);
                acc[p][2] = f2fma(a, p2, acc[p][2]);
                acc[p][3] = f2fma(a, p3, acc[p][3]);
            }
        }
    }
    // epilogue: unpack row-pairs, store + fused scores.
#pragma unroll
    for (int p = 0; p < 4; p++) {
        float lo[4], hi[4];
#pragma unroll
        for (int cc = 0; cc < 4; cc++) up2(acc[p][cc], lo[cc], hi[cc]);
#pragma unroll
        for (int half = 0; half < 2; half++) {
            const float* v = half ? hi : lo;
            int n = row0 + ty * 8 + 2 * p + half;
            float pas = 0.f, pad = 0.f;
#pragma unroll
            for (int cc = 0; cc < 4; cc++) {
                pas = fmaf(v[cc], sa[tx * 4 + cc], pas);
                pad = fmaf(v[cc], sd[tx * 4 + cc], pad);
            }
            pas += __shfl_xor_sync(0xffffffffu, pas, 1);
            pas += __shfl_xor_sync(0xffffffffu, pas, 2);
            pas += __shfl_xor_sync(0xffffffffu, pas, 4);
            pad += __shfl_xor_sync(0xffffffffu, pad, 1);
            pad += __shfl_xor_sync(0xffffffffu, pad, 2);
            pad += __shfl_xor_sync(0xffffffffu, pad, 4);
            if (n < NN_) {
                *(float4*)&g_xl1[n * HC_ + tx * 4] =
                    make_float4(v[0], v[1], v[2], v[3]);
                if (tx == 0 || tx == 8) {        // tx<8: head0, tx>=8: head1
                    int h = tx >> 3;
                    g_as1[n * 2 + h] = pas;
                    g_ad1[n * 2 + h] = pad;
                }
            }
        }
    }
}

// ---------------- GEMM2 + scores2 fused (FFMA2, 8x8, BM=512) ----------------
#define XP2_ 516
__global__ void __launch_bounds__(256, 2)
gemm2_kernel(const float* __restrict__ W2,
             const float* __restrict__ as, const float* __restrict__ ad) {
    __shared__ float ws[HC_ * OC_];    //  8 KB, [k][c]
    __shared__ float xs[8 * XP2_];     // 16.5 KB, [k_local][row(padded)]
    __shared__ float sa[OC_], sd[OC_];
    int t = threadIdx.x;
    int tx = t & 3, ty = t >> 2;
    int row0 = blockIdx.x * 512;

    if (t < OC_) { sa[t] = as[t]; sd[t] = ad[t]; }
    for (int i = t; i < HC_ * OC_ / 4; i += 256)
        ((float4*)ws)[i] = ((const float4*)W2)[i];

    int rr[4], qq[4], gg[4];
#pragma unroll
    for (int rep = 0; rep < 4; rep++) {
        int idx = t + rep * 256;
        rr[rep] = idx >> 1; qq[rep] = idx & 1; gg[rep] = row0 + rr[rep];
    }
    const float4 z4 = make_float4(0.f, 0.f, 0.f, 0.f);
    float4 pre[4];
#pragma unroll
    for (int rep = 0; rep < 4; rep++)
        pre[rep] = (gg[rep] < NN_) ? ((const float4*)g_h1)[gg[rep] * 16 + qq[rep]] : z4;

    ull acc[4][8];
#pragma unroll
    for (int a = 0; a < 4; a++)
#pragma unroll
        for (int b = 0; b < 8; b++) acc[a][b] = 0ull;

    for (int c = 0; c < 8; c++) {      // 8 chunks of 8 k
        __syncthreads();
#pragma unroll
        for (int rep = 0; rep < 4; rep++) {
            int r = rr[rep], q = qq[rep];
            xs[(4 * q + 0) * XP2_ + r] = pre[rep].x;
            xs[(4 * q + 1) * XP2_ + r] = pre[rep].y;
            xs[(4 * q + 2) * XP2_ + r] = pre[rep].z;
            xs[(4 * q + 3) * XP2_ + r] = pre[rep].w;
        }
        __syncthreads();
        if (c < 7) {
#pragma unroll
            for (int rep = 0; rep < 4; rep++)
                pre[rep] = (gg[rep] < NN_)
                    ? ((const float4*)g_h1)[gg[rep] * 16 + (c + 1) * 2 + qq[rep]] : z4;
        }
#pragma unroll
        for (int k = 0; k < 8; k++) {
            const ull* ap = (const ull*)&xs[k * XP2_ + ty * 8];
            ull a0 = ap[0], a1 = ap[1], a2 = ap[2], a3 = ap[3];
            const float* wr = &ws[(c * 8 + k) * OC_ + tx * 8];
            float4 b0 = *(const float4*)&wr[0];
            float4 b1 = *(const float4*)&wr[4];
            ull p0 = pk2(b0.x, b0.x), p1 = pk2(b0.y, b0.y);
            ull p2 = pk2(b0.z, b0.z), p3 = pk2(b0.w, b0.w);
            ull p4 = pk2(b1.x, b1.x), p5 = pk2(b1.y, b1.y);
            ull p6 = pk2(b1.z, b1.z), p7 = pk2(b1.w, b1.w);
            ull av[4] = {a0, a1, a2, a3};
#pragma unroll
            for (int p = 0; p < 4; p++) {
                ull a = av[p];
                acc[p][0] = f2fma(a, p0, acc[p][0]);
                acc[p][1] = f2fma(a, p1, acc[p][1]);
                acc[p][2] = f2fma(a, p2, acc[p][2]);
                acc[p][3] = f2fma(a, p3, acc[p][3]);
                acc[p][4] = f2fma(a, p4, acc[p][4]);
                acc[p][5] = f2fma(a, p5, acc[p][5]);
                acc[p][6] = f2fma(a, p6, acc[p][6]);
                acc[p][7] = f2fma(a, p7, acc[p][7]);
            }
        }
    }
#pragma unroll
    for (int p = 0; p < 4; p++) {
        float lo[8], hi[8];
#pragma unroll
        for (int cc = 0; cc < 8; cc++) up2(acc[p][cc], lo[cc], hi[cc]);
#pragma unroll
        for (int half = 0; half < 2; half++) {
            const float* v = half ? hi : lo;
            int n = row0 + ty * 8 + 2 * p + half;
            float pas = 0.f, pad = 0.f;
#pragma unroll
            for (int cc = 0; cc < 8; cc++) {
                pas = fmaf(v[cc], sa[tx * 8 + cc], pas);
                pad = fmaf(v[cc], sd[tx * 8 + cc], pad);
            }
            pas += __shfl_xor_sync(0xffffffffu, pas, 1);
            pas += __shfl_xor_sync(0xffffffffu, pas, 2);
            pad += __shfl_xor_sync(0xffffffffu, pad, 1);
            pad += __shfl_xor_sync(0xffffffffu, pad, 2);
            if (n < NN_) {
                *(float4*)&g_xl2[n * OC_ + tx * 8] =
                    make_float4(v[0], v[1], v[2], v[3]);
                *(float4*)&g_xl2[n * OC_ + tx * 8 + 4] =
                    make_float4(v[4], v[5], v[6], v[7]);
                if (tx == 0) { g_as2[n] = pas; g_ad2[n] = pad; }
            }
        }
    }
}

// ---------------- layer-1 aggregation (exp fused in staging lane) -----------
// Staging lane j: load src, gather as1[src] (8B), compute both-head exps
// (dst == n, so ad1[n] is warp-local). Inner loop reads via LDS broadcast.
__global__ void __launch_bounds__(256, 4)
agg1_kernel(const float* __restrict__ b1) {
    __shared__ float4 stg[8][32];
    int g = blockIdx.x * blockDim.x + threadIdx.x;
    int n = g >> 5, lane = g & 31, wid = (threadIdx.x >> 5);
    if (n >= NN_) return;
    float2 ad1n = ((const float2*)g_ad1)[n];
    float2 as1n = ((const float2*)g_as1)[n];
    float ex0 = __expf(lrelu(as1n.x + ad1n.x));   // self loop
    float ex1 = __expf(lrelu(as1n.y + ad1n.y));
    float den0 = ex0, den1 = ex1;
    const float2* xl = (const float2*)g_xl1;
    float2 v = xl[n * 32 + lane];
    bool h0 = lane < 16;
    float exm = h0 ? ex0 : ex1;
    float ax = exm * v.x, ay = exm * v.y;
    int st = g_ptr[n], de = g_deg[n];
    for (int base = 0; base < de; base += 32) {
        int m = min(32, de - base);
        if (lane < m) {
            int s = g_esrc[st + base + lane];
            float2 a = ((const float2*)g_as1)[s];            // 8B random
            stg[wid][lane] = make_float4(__int_as_float(s),
                                         __expf(lrelu(a.x + ad1n.x)),
                                         __expf(lrelu(a.y + ad1n.y)), 0.f);
        }
        __syncwarp();
#pragma unroll 4
        for (int j = 0; j < m; j++) {
            float4 r = stg[wid][j];              // LDS broadcast
            int s = __float_as_int(r.x);
            den0 += r.y; den1 += r.z;
            float2 w = xl[s * 32 + lane];        // 256B row gather
            float fm = h0 ? r.y : r.z;
            ax = fmaf(fm, w.x, ax);
            ay = fmaf(fm, w.y, ay);
        }
        __syncwarp();
    }
    float den = h0 ? den0 : den1;
    float inv = 1.f / (den + 1e-16f);
    float bx = b1[lane * 2], by = b1[lane * 2 + 1];
    float2 o;
    o.x = fmaxf(fmaf(ax, inv, bx), 0.f);   // bias + ReLU fused
    o.y = fmaxf(fmaf(ay, inv, by), 0.f);
    ((float2*)g_h1)[n * 32 + lane] = o;
}

// ---------------- layer-2 aggregation (exp fused, smem-staged) --------------
__global__ void __launch_bounds__(256, 4)
agg2_kernel(const float* __restrict__ b2, float* __restrict__ out) {
    __shared__ float2 stg[8][32];
    int g = blockIdx.x * blockDim.x + threadIdx.x;
    int n = g >> 5, lane = g & 31, wid = (threadIdx.x >> 5);
    if (n >= NN_) return;
    float ad2n = g_ad2[n];
    float ex = __expf(lrelu(g_as2[n] + ad2n));   // self loop
    float den = ex;
    float acc = ex * g_xl2[n * OC_ + lane];
    int st = g_ptr[n], de = g_deg[n];
    for (int base = 0; base < de; base += 32) {
        int m = min(32, de - base);
        if (lane < m) {
            int s = g_esrc[st + base + lane];
            float e = __expf(lrelu(g_as2[s] + ad2n));
            stg[wid][lane] = make_float2(__int_as_float(s), e);
        }
        __syncwarp();
#pragma unroll 4
        for (int j = 0; j < m; j++) {
            float2 r = stg[wid][j];              // LDS broadcast
            int s = __float_as_int(r.x);
            den += r.y;
            acc = fmaf(r.y, g_xl2[s * OC_ + lane], acc);   // 128B row gather
        }
        __syncwarp();
    }
    out[n * OC_ + lane] = acc / (den + 1e-16f) + b2[lane];
}

// ---------------- launch ----------------
extern "C" void kernel_launch(void* const* d_in, const int* in_sizes, int n_in,
                              void* d_out, int out_size) {
    // size-keyed input remap with positional fallback
    const float* x = 0; const int* ei = 0;
    const float* W1 = 0; const float* W2 = 0;
    const float* a64[3] = {0, 0, 0}; int n64 = 0;
    const float* a32[3] = {0, 0, 0}; int n32 = 0;
    for (int i = 0; i < n_in; i++) {
        int sz = in_sizes[i];
        if      (sz == NN_ * INF_) x  = (const float*)d_in[i];
        else if (sz == 2 * NE_)    ei = (const int*)  d_in[i];
        else if (sz == INF_ * HC_) W1 = (const float*)d_in[i];
        else if (sz == HC_ * OC_)  W2 = (const float*)d_in[i];
        else if (sz == HC_) { if (n64 < 3) a64[n64++] = (const float*)d_in[i]; }
        else if (sz == OC_) { if (n32 < 3) a32[n32++] = (const float*)d_in[i]; }
    }
    if (!x)  x  = (const float*)d_in[0];
    if (!ei) ei = (const int*)  d_in[1];
    if (!W1) W1 = (const float*)d_in[2];
    if (!W2) W2 = (const float*)d_in[6];
    const float* as1 = a64[0] ? a64[0] : (const float*)d_in[3];
    const float* ad1 = a64[1] ? a64[1] : (const float*)d_in[4];
    const float* b1  = a64[2] ? a64[2] : (const float*)d_in[5];
    const float* as2 = a32[0] ? a32[0] : (const float*)d_in[7];
    const float* ad2 = a32[1] ? a32[1] : (const float*)d_in[8];
    const float* b2  = a32[2] ? a32[2] : (const float*)d_in[9];
    float* out = (float*)d_out;

    const int* srcp = ei;
    const int* dstp = ei + NE_;

    const int NB  = (NN_ + 255) / 256;         // node blocks
    const int EB  = (NE_ + 255) / 256;         // edge blocks
    const int G1  = (NN_ + 127) / 128;         // 782 gemm1 blocks (128 rows)
    const int G2  = (NN_ + 511) / 512;         // 196 gemm2 blocks (512 rows)
    const int WB  = (NN_ * 32 + 255) / 256;    // 12500 warp-per-node blocks

    // sequential pipeline (R13 fork experiment regressed: L2 contention)
    prep_kernel<<<NB, 256>>>();
    hist_kernel<<<EB, 256>>>(dstp);
    ptr_kernel<<<NB, 256>>>();
    scatter_kernel<<<EB, 256>>>(srcp, dstp);   // no longer needs scores

    gemm1_kernel<<<G1, 256>>>(x, W1, as1, ad1);
    agg1_kernel<<<WB, 256>>>(b1);

    gemm2_kernel<<<G2, 256>>>(W2, as2, ad2);
    agg2_kernel<<<WB, 256>>>(b2, out);

    (void)n_in; (void)out_size;
}

// round 17
// speedup vs baseline: 1.5653x; 1.0247x over previous
#include <cuda_runtime.h>

#define NN_ 100000
#define NE_ 1600000
#define INF_ 128
#define HC_ 64
#define OC_ 32

// ---------------- scratch (static device globals; no allocation) ----------------
__device__ __align__(16) float  g_xl1[NN_ * HC_];   // x @ W1     (25.6 MB)
__device__ __align__(16) float  g_h1 [NN_ * HC_];   // relu(gat1) (25.6 MB)
__device__ __align__(16) float  g_xl2[NN_ * OC_];   // h @ W2     (12.8 MB)
__device__ __align__(8) float  g_as1[NN_ * 2];      // layer1 per-node scores
__device__ __align__(8) float  g_ad1[NN_ * 2];
__device__ float  g_as2[NN_];
__device__ float  g_ad2[NN_];
__device__ int    g_deg[NN_];
__device__ int    g_ptr[NN_];
__device__ int    g_total;
__device__ int    g_rank[NE_];                      // edge rank within dst bin
__device__ int    g_esrc[NE_];                      // 4B/edge record (src only)

__device__ __forceinline__ float lrelu(float x) { return x > 0.f ? x : 0.2f * x; }

typedef unsigned long long ull;
__device__ __forceinline__ ull pk2(float x, float y) {
    ull r; asm("mov.b64 %0,{%1,%2};" : "=l"(r) : "f"(x), "f"(y)); return r;
}
__device__ __forceinline__ void up2(ull v, float& x, float& y) {
    asm("mov.b64 {%0,%1},%2;" : "=f"(x), "=f"(y) : "l"(v));
}
// packed fp32x2 FMA (FFMA2): d.lo=fma(a.lo,b.lo,c.lo), d.hi likewise
__device__ __forceinline__ ull f2fma(ull a, ull b, ull c) {
    ull d; asm("fma.rn.f32x2 %0,%1,%2,%3;" : "=l"(d) : "l"(a), "l"(b), "l"(c)); return d;
}

// ---------------- CSR build (no global scans; bins in arbitrary order) -------
__global__ void prep_kernel() {
    int i = blockIdx.x * blockDim.x + threadIdx.x;
    if (i < NN_) g_deg[i] = 0;
    if (i == 0) g_total = 0;
}
// hist's atomic return value IS the edge's rank in its bin — store it
// (coalesced) so scatter needs no atomic at all.
__global__ void hist_kernel(const int* __restrict__ dst) {
    int i = blockIdx.x * blockDim.x + threadIdx.x;
    if (i < NE_) g_rank[i] = atomicAdd(&g_deg[dst[i]], 1);
}
// Hierarchical bin offsets: block-local smem scan + ONE atomic per block.
__global__ void ptr_kernel() {
    __shared__ int sdeg[256];
    __shared__ int sbase;
    int t = threadIdx.x;
    int i = blockIdx.x * 256 + t;
    int d = (i < NN_) ? g_deg[i] : 0;
    sdeg[t] = d;
    __syncthreads();
    for (int off = 1; off < 256; off <<= 1) {   // Hillis-Steele inclusive scan
        int u = (t >= off) ? sdeg[t - off] : 0;
        __syncthreads();
        sdeg[t] += u;
        __syncthreads();
    }
    if (t == 255) sbase = atomicAdd(&g_total, sdeg[255]);
    __syncthreads();
    if (i < NN_) g_ptr[i] = sbase + sdeg[t] - d;   // exclusive prefix + base
}
// scatter: atomic-free — position = bin base + precomputed rank.
__global__ void scatter_kernel(const int* __restrict__ src,
                               const int* __restrict__ dst) {
    int i = blockIdx.x * blockDim.x + threadIdx.x;
    if (i >= NE_) return;
    int p = g_ptr[dst[i]] + g_rank[i];
    if (p < 0 || p >= NE_) return;               // defensive: never corrupt memory
    g_esrc[p] = src[i];
}

// ---------------- GEMM1 + scores1 fused (FFMA2, 8x4 tile, 4 CTAs/SM) --------
#define XP_ 132
__global__ void __launch_bounds__(256, 4)
gemm1_kernel(const float* __restrict__ x, const float* __restrict__ W1,
             const float* __restrict__ as, const float* __restrict__ ad) {
    __shared__ float ws[INF_ * HC_];   // 32 KB, [k][c]
    __shared__ float xs[8 * XP_];      // 4.2 KB, [k_local][row(padded)]
    __shared__ float sa[HC_], sd[HC_];
    int t = threadIdx.x;
    int tx = t & 15, ty = t >> 4;
    int row0 = blockIdx.x * 128;

    if (t < HC_) { sa[t] = as[t]; sd[t] = ad[t]; }
    for (int i = t; i < INF_ * HC_ / 4; i += 256)
        ((float4*)ws)[i] = ((const float4*)W1)[i];

    int r0 = t >> 1, q0 = t & 1;
    int gr0 = row0 + r0;
    const float4 z4 = make_float4(0.f, 0.f, 0.f, 0.f);
    float4 pre0 = (gr0 < NN_) ? ((const float4*)x)[gr0 * 32 + q0] : z4;

    ull acc[4][4];                     // [row-pair][col]
#pragma unroll
    for (int a = 0; a < 4; a++)
#pragma unroll
        for (int b = 0; b < 4; b++) acc[a][b] = 0ull;

    for (int c = 0; c < 16; c++) {     // 16 chunks of 8 k
        __syncthreads();
        xs[(4 * q0 + 0) * XP_ + r0] = pre0.x;   // transpose into [k][row]
        xs[(4 * q0 + 1) * XP_ + r0] = pre0.y;
        xs[(4 * q0 + 2) * XP_ + r0] = pre0.z;
        xs[(4 * q0 + 3) * XP_ + r0] = pre0.w;
        __syncthreads();
        if (c < 15)
            pre0 = (gr0 < NN_) ? ((const float4*)x)[gr0 * 32 + (c + 1) * 2 + q0] : z4;
#pragma unroll
        for (int k = 0; k < 8; k++) {
            const ull* ap = (const ull*)&xs[k * XP_ + ty * 8];   // 4 row-pairs
            ull a0 = ap[0], a1 = ap[1], a2 = ap[2], a3 = ap[3];
            float4 b = *(const float4*)&ws[(c * 8 + k) * HC_ + tx * 4];
            ull p0 = pk2(b.x, b.x), p1 = pk2(b.y, b.y);
            ull p2 = pk2(b.z, b.z), p3 = pk2(b.w, b.w);
            ull av[4] = {a0, a1, a2, a3};
#pragma unroll
            for (int p = 0; p < 4; p++) {
                ull a = av[p];
                acc[p][0] = f2fma(a, p0, acc[p][0]);
                acc[p][1] = f2fma(a, p1, acc[p][1]);
                acc[p][2] = f2fma(a, p2, acc[p][2]);
                acc[p][3] = f2fma(a, p3, acc[p][3]);
            }
        }
    }
    // epilogue: unpack row-pairs, store + fused scores.
#pragma unroll
    for (int p = 0; p < 4; p++) {
        float lo[4], hi[4];
#pragma unroll
        for (int cc = 0; cc < 4; cc++) up2(acc[p][cc], lo[cc], hi[cc]);
#pragma unroll
        for (int half = 0; half < 2; half++) {
            const float* v = half ? hi : lo;
            int n = row0 + ty * 8 + 2 * p + half;
            float pas = 0.f, pad = 0.f;
#pragma unroll
            for (int cc = 0; cc < 4; cc++) {
                pas = fmaf(v[cc], sa[tx * 4 + cc], pas);
                pad = fmaf(v[cc], sd[tx * 4 + cc], pad);
            }
            pas += __shfl_xor_sync(0xffffffffu, pas, 1);
            pas += __shfl_xor_sync(0xffffffffu, pas, 2);
            pas += __shfl_xor_sync(0xffffffffu, pas, 4);
            pad += __shfl_xor_sync(0xffffffffu, pad, 1);
            pad += __shfl_xor_sync(0xffffffffu, pad, 2);
            pad += __shfl_xor_sync(0xffffffffu, pad, 4);
            if (n < NN_) {
                *(float4*)&g_xl1[n * HC_ + tx * 4] =
                    make_float4(v[0], v[1], v[2], v[3]);
                if (tx == 0 || tx == 8) {        // tx<8: head0, tx>=8: head1
                    int h = tx >> 3;
                    g_as1[n * 2 + h] = pas;
                    g_ad1[n * 2 + h] = pad;
                }
            }
        }
    }
}

// ---------------- GEMM2 + scores2 fused (FFMA2, 8x8, BM=512) ----------------
#define XP2_ 516
__global__ void __launch_bounds__(256, 2)
gemm2_kernel(const float* __restrict__ W2,
             const float* __restrict__ as, const float* __restrict__ ad) {
    __shared__ float ws[HC_ * OC_];    //  8 KB, [k][c]
    __shared__ float xs[8 * XP2_];     // 16.5 KB, [k_local][row(padded)]
    __shared__ float sa[OC_], sd[OC_];
    int t = threadIdx.x;
    int tx = t & 3, ty = t >> 2;
    int row0 = blockIdx.x * 512;

    if (t < OC_) { sa[t] = as[t]; sd[t] = ad[t]; }
    for (int i = t; i < HC_ * OC_ / 4; i += 256)
        ((float4*)ws)[i] = ((const float4*)W2)[i];

    int rr[4], qq[4], gg[4];
#pragma unroll
    for (int rep = 0; rep < 4; rep++) {
        int idx = t + rep * 256;
        rr[rep] = idx >> 1; qq[rep] = idx & 1; gg[rep] = row0 + rr[rep];
    }
    const float4 z4 = make_float4(0.f, 0.f, 0.f, 0.f);
    float4 pre[4];
#pragma unroll
    for (int rep = 0; rep < 4; rep++)
        pre[rep] = (gg[rep] < NN_) ? ((const float4*)g_h1)[gg[rep] * 16 + qq[rep]] : z4;

    ull acc[4][8];
#pragma unroll
    for (int a = 0; a < 4; a++)
#pragma unroll
        for (int b = 0; b < 8; b++) acc[a][b] = 0ull;

    for (int c = 0; c < 8; c++) {      // 8 chunks of 8 k
        __syncthreads();
#pragma unroll
        for (int rep = 0; rep < 4; rep++) {
            int r = rr[rep], q = qq[rep];
            xs[(4 * q + 0) * XP2_ + r] = pre[rep].x;
            xs[(4 * q + 1) * XP2_ + r] = pre[rep].y;
            xs[(4 * q + 2) * XP2_ + r] = pre[rep].z;
            xs[(4 * q + 3) * XP2_ + r] = pre[rep].w;
        }
        __syncthreads();
        if (c < 7) {
#pragma unroll
            for (int rep = 0; rep < 4; rep++)
                pre[rep] = (gg[rep] < NN_)
                    ? ((const float4*)g_h1)[gg[rep] * 16 + (c + 1) * 2 + qq[rep]] : z4;
        }
#pragma unroll
        for (int k = 0; k < 8; k++) {
            const ull* ap = (const ull*)&xs[k * XP2_ + ty * 8];
            ull a0 = ap[0], a1 = ap[1], a2 = ap[2], a3 = ap[3];
            const float* wr = &ws[(c * 8 + k) * OC_ + tx * 8];
            float4 b0 = *(const float4*)&wr[0];
            float4 b1 = *(const float4*)&wr[4];
            ull p0 = pk2(b0.x, b0.x), p1 = pk2(b0.y, b0.y);
            ull p2 = pk2(b0.z, b0.z), p3 = pk2(b0.w, b0.w);
            ull p4 = pk2(b1.x, b1.x), p5 = pk2(b1.y, b1.y);
            ull p6 = pk2(b1.z, b1.z), p7 = pk2(b1.w, b1.w);
            ull av[4] = {a0, a1, a2, a3};
#pragma unroll
            for (int p = 0; p < 4; p++) {
                ull a = av[p];
                acc[p][0] = f2fma(a, p0, acc[p][0]);
                acc[p][1] = f2fma(a, p1, acc[p][1]);
                acc[p][2] = f2fma(a, p2, acc[p][2]);
                acc[p][3] = f2fma(a, p3, acc[p][3]);
                acc[p][4] = f2fma(a, p4, acc[p][4]);
                acc[p][5] = f2fma(a, p5, acc[p][5]);
                acc[p][6] = f2fma(a, p6, acc[p][6]);
                acc[p][7] = f2fma(a, p7, acc[p][7]);
            }
        }
    }
#pragma unroll
    for (int p = 0; p < 4; p++) {
        float lo[8], hi[8];
#pragma unroll
        for (int cc = 0; cc < 8; cc++) up2(acc[p][cc], lo[cc], hi[cc]);
#pragma unroll
        for (int half = 0; half < 2; half++) {
            const float* v = half ? hi : lo;
            int n = row0 + ty * 8 + 2 * p + half;
            float pas = 0.f, pad = 0.f;
#pragma unroll
            for (int cc = 0; cc < 8; cc++) {
                pas = fmaf(v[cc], sa[tx * 8 + cc], pas);
                pad = fmaf(v[cc], sd[tx * 8 + cc], pad);
            }
            pas += __shfl_xor_sync(0xffffffffu, pas, 1);
            pas += __shfl_xor_sync(0xffffffffu, pas, 2);
            pad += __shfl_xor_sync(0xffffffffu, pad, 1);
            pad += __shfl_xor_sync(0xffffffffu, pad, 2);
            if (n < NN_) {
                *(float4*)&g_xl2[n * OC_ + tx * 8] =
                    make_float4(v[0], v[1], v[2], v[3]);
                *(float4*)&g_xl2[n * OC_ + tx * 8 + 4] =
                    make_float4(v[4], v[5], v[6], v[7]);
                if (tx == 0) { g_as2[n] = pas; g_ad2[n] = pad; }
            }
        }
    }
}

// ---------------- layer-1 aggregation (exp fused in staging lane) -----------
__global__ void __launch_bounds__(256, 4)
agg1_kernel(const float* __restrict__ b1) {
    __shared__ float4 stg[8][32];
    int g = blockIdx.x * blockDim.x + threadIdx.x;
    int n = g >> 5, lane = g & 31, wid = (threadIdx.x >> 5);
    if (n >= NN_) return;
    float2 ad1n = ((const float2*)g_ad1)[n];
    float2 as1n = ((const float2*)g_as1)[n];
    float ex0 = __expf(lrelu(as1n.x + ad1n.x));   // self loop
    float ex1 = __expf(lrelu(as1n.y + ad1n.y));
    float den0 = ex0, den1 = ex1;
    const float2* xl = (const float2*)g_xl1;
    float2 v = xl[n * 32 + lane];
    bool h0 = lane < 16;
    float exm = h0 ? ex0 : ex1;
    float ax = exm * v.x, ay = exm * v.y;
    int st = g_ptr[n], de = g_deg[n];
    for (int base = 0; base < de; base += 32) {
        int m = min(32, de - base);
        if (lane < m) {
            int s = g_esrc[st + base + lane];
            float2 a = ((const float2*)g_as1)[s];            // 8B random
            stg[wid][lane] = make_float4(__int_as_float(s),
                                         __expf(lrelu(a.x + ad1n.x)),
                                         __expf(lrelu(a.y + ad1n.y)), 0.f);
        }
        __syncwarp();
#pragma unroll 4
        for (int j = 0; j < m; j++) {
            float4 r = stg[wid][j];              // LDS broadcast
            int s = __float_as_int(r.x);
            den0 += r.y; den1 += r.z;
            float2 w = xl[s * 32 + lane];        // 256B row gather
            float fm = h0 ? r.y : r.z;
            ax = fmaf(fm, w.x, ax);
            ay = fmaf(fm, w.y, ay);
        }
        __syncwarp();
    }
    float den = h0 ? den0 : den1;
    float inv = 1.f / (den + 1e-16f);
    float bx = b1[lane * 2], by = b1[lane * 2 + 1];
    float2 o;
    o.x = fmaxf(fmaf(ax, inv, bx), 0.f);   // bias + ReLU fused
    o.y = fmaxf(fmaf(ay, inv, by), 0.f);
    ((float2*)g_h1)[n * 32 + lane] = o;
}

// ---------------- layer-2 aggregation (exp fused, smem-staged) --------------
__global__ void __launch_bounds__(256, 4)
agg2_kernel(const float* __restrict__ b2, float* __restrict__ out) {
    __shared__ float2 stg[8][32];
    int g = blockIdx.x * blockDim.x + threadIdx.x;
    int n = g >> 5, lane = g & 31, wid = (threadIdx.x >> 5);
    if (n >= NN_) return;
    float ad2n = g_ad2[n];
    float ex = __expf(lrelu(g_as2[n] + ad2n));   // self loop
    float den = ex;
    float acc = ex * g_xl2[n * OC_ + lane];
    int st = g_ptr[n], de = g_deg[n];
    for (int base = 0; base < de; base += 32) {
        int m = min(32, de - base);
        if (lane < m) {
            int s = g_esrc[st + base + lane];
            float e = __expf(lrelu(g_as2[s] + ad2n));
            stg[wid][lane] = make_float2(__int_as_float(s), e);
        }
        __syncwarp();
#pragma unroll 4
        for (int j = 0; j < m; j++) {
            float2 r = stg[wid][j];              // LDS broadcast
            int s = __float_as_int(r.x);
            den += r.y;
            acc = fmaf(r.y, g_xl2[s * OC_ + lane], acc);   // 128B row gather
        }
        __syncwarp();
    }
    out[n * OC_ + lane] = acc / (den + 1e-16f) + b2[lane];
}

// ---------------- launch ----------------
extern "C" void kernel_launch(void* const* d_in, const int* in_sizes, int n_in,
                              void* d_out, int out_size) {
    // size-keyed input remap with positional fallback
    const float* x = 0; const int* ei = 0;
    const float* W1 = 0; const float* W2 = 0;
    const float* a64[3] = {0, 0, 0}; int n64 = 0;
    const float* a32[3] = {0, 0, 0}; int n32 = 0;
    for (int i = 0; i < n_in; i++) {
        int sz = in_sizes[i];
        if      (sz == NN_ * INF_) x  = (const float*)d_in[i];
        else if (sz == 2 * NE_)    ei = (const int*)  d_in[i];
        else if (sz == INF_ * HC_) W1 = (const float*)d_in[i];
        else if (sz == HC_ * OC_)  W2 = (const float*)d_in[i];
        else if (sz == HC_) { if (n64 < 3) a64[n64++] = (const float*)d_in[i]; }
        else if (sz == OC_) { if (n32 < 3) a32[n32++] = (const float*)d_in[i]; }
    }
    if (!x)  x  = (const float*)d_in[0];
    if (!ei) ei = (const int*)  d_in[1];
    if (!W1) W1 = (const float*)d_in[2];
    if (!W2) W2 = (const float*)d_in[6];
    const float* as1 = a64[0] ? a64[0] : (const float*)d_in[3];
    const float* ad1 = a64[1] ? a64[1] : (const float*)d_in[4];
    const float* b1  = a64[2] ? a64[2] : (const float*)d_in[5];
    const float* as2 = a32[0] ? a32[0] : (const float*)d_in[7];
    const float* ad2 = a32[1] ? a32[1] : (const float*)d_in[8];
    const float* b2  = a32[2] ? a32[2] : (const float*)d_in[9];
    float* out = (float*)d_out;

    const int* srcp = ei;
    const int* dstp = ei + NE_;

    const int NB  = (NN_ + 255) / 256;         // node blocks
    const int EB  = (NE_ + 255) / 256;         // edge blocks
    const int G1  = (NN_ + 127) / 128;         // 782 gemm1 blocks (128 rows)
    const int G2  = (NN_ + 511) / 512;         // 196 gemm2 blocks (512 rows)
    const int WB  = (NN_ * 32 + 255) / 256;    // 12500 warp-per-node blocks

    // sequential pipeline (R13 fork experiment regressed: L2 contention)
    prep_kernel<<<NB, 256>>>();
    hist_kernel<<<EB, 256>>>(dstp);            // also assigns per-edge ranks
    ptr_kernel<<<NB, 256>>>();
    scatter_kernel<<<EB, 256>>>(srcp, dstp);   // atomic-free placement

    gemm1_kernel<<<G1, 256>>>(x, W1, as1, ad1);
    agg1_kernel<<<WB, 256>>>(b1);

    gemm2_kernel<<<G2, 256>>>(W2, as2, ad2);
    agg2_kernel<<<WB, 256>>>(b2, out);

    (void)n_in; (void)out_size;
}